// round 15
// baseline (speedup 1.0000x reference)
#include <cuda_runtime.h>
#include <math.h>

// Shapes (fixed by the problem)
#define B_ 64
#define S_ 2048
#define H_ 1024
#define E_ 512
#define V_ 50257

// ---------------------------------------------------------------------------
// Device scratch (allocation-free: __device__ globals).
// ---------------------------------------------------------------------------
__device__ float g_gi_part[8 * B_ * 3 * H_];      // 8 K-splits of x @ w_ih^T
__device__ float g_gh_part[8 * B_ * 3 * H_];      // 8 K-splits of h @ w_hh^T
__device__ float g_cat_part[16 * B_ * H_];        // 16 K-splits of concat GEMM
__device__ float g_concat_in[B_ * 2 * H_];
__device__ float g_concat_out[B_ * H_];
__device__ float g_energies[B_ * S_];
__device__ float2 g_ml[B_ * 16];
__device__ float g_ctxp[(size_t)B_ * 16 * H_];

// ---------------------------------------------------------------------------
// Generic small-GEMM (used for the concat projection).
// ---------------------------------------------------------------------------
__global__ __launch_bounds__(256) void gemm64(
    const float* __restrict__ A, const float* __restrict__ Bw,
    float* __restrict__ C, int N, int K, int klen,
    const float* __restrict__ bias, int act)
{
    __shared__ float As[16][64];
    __shared__ float Bs[16][64];
    const int tid = threadIdx.x;
    const int tx = tid & 15, ty = tid >> 4;
    const int n0 = blockIdx.x * 64;
    const int k0 = blockIdx.y * klen;
    C += (size_t)blockIdx.y * 64 * N;

    const int a_r = tid >> 2;
    const int a_c = (tid & 3) << 2;

    float acc[4][4];
#pragma unroll
    for (int i = 0; i < 4; i++)
#pragma unroll
        for (int j = 0; j < 4; j++) acc[i][j] = 0.f;

    for (int kk0 = 0; kk0 < klen; kk0 += 16) {
        const int kb = k0 + kk0 + a_c;
        float4 av = *(const float4*)(A + (size_t)a_r * K + kb);
        float4 bv = make_float4(0.f, 0.f, 0.f, 0.f);
        const int nr = n0 + a_r;
        if (nr < N) bv = *(const float4*)(Bw + (size_t)nr * K + kb);

        __syncthreads();
        As[a_c + 0][a_r] = av.x; As[a_c + 1][a_r] = av.y;
        As[a_c + 2][a_r] = av.z; As[a_c + 3][a_r] = av.w;
        Bs[a_c + 0][a_r] = bv.x; Bs[a_c + 1][a_r] = bv.y;
        Bs[a_c + 2][a_r] = bv.z; Bs[a_c + 3][a_r] = bv.w;
        __syncthreads();

#pragma unroll
        for (int kk = 0; kk < 16; kk++) {
            float4 a  = *(const float4*)&As[kk][ty << 2];
            float4 bb = *(const float4*)&Bs[kk][tx << 2];
            float am[4] = {a.x, a.y, a.z, a.w};
            float bn[4] = {bb.x, bb.y, bb.z, bb.w};
#pragma unroll
            for (int i = 0; i < 4; i++)
#pragma unroll
                for (int j = 0; j < 4; j++)
                    acc[i][j] = fmaf(am[i], bn[j], acc[i][j]);
        }
    }

#pragma unroll
    for (int i = 0; i < 4; i++) {
        const int m = (ty << 2) + i;
#pragma unroll
        for (int j = 0; j < 4; j++) {
            const int n = n0 + (tx << 2) + j;
            if (n < N) {
                float v = acc[i][j];
                if (bias) v += bias[n];
                if (act) v = tanhf(v);
                C[(size_t)m * N + n] = v;
            }
        }
    }
}

// ---------------------------------------------------------------------------
// Merged GRU GEMMs: ONE launch computes gi (z=0, K=512) and gh (z=1, K=1024),
// each 8-way K-split -> 768 CTAs total (vs 2 x 192): ~2.6x more resident
// FMA-issuing warps for these issue-bound small GEMMs, one less launch.
// N = 3072 exact (48 x 64), no bounds checks.
// ---------------------------------------------------------------------------
__global__ __launch_bounds__(256) void gemm_gru(
    const float* __restrict__ x,    const float* __restrict__ h0,
    const float* __restrict__ w_ih, const float* __restrict__ w_hh)
{
    __shared__ float As[16][64];
    __shared__ float Bs[16][64];
    const int z = blockIdx.z;
    const float* A  = z ? h0   : x;
    const float* Bw = z ? w_hh : w_ih;
    float* C = (z ? g_gh_part : g_gi_part) + (size_t)blockIdx.y * 64 * 3 * H_;
    const int K = z ? 1024 : 512;
    const int klen = K >> 3;                 // 8 splits
    const int k0 = blockIdx.y * klen;
    const int n0 = blockIdx.x * 64;

    const int tid = threadIdx.x;
    const int tx = tid & 15, ty = tid >> 4;
    const int a_r = tid >> 2;
    const int a_c = (tid & 3) << 2;

    float acc[4][4];
#pragma unroll
    for (int i = 0; i < 4; i++)
#pragma unroll
        for (int j = 0; j < 4; j++) acc[i][j] = 0.f;

    for (int kk0 = 0; kk0 < klen; kk0 += 16) {
        const int kb = k0 + kk0 + a_c;
        float4 av = *(const float4*)(A + (size_t)a_r * K + kb);
        float4 bv = *(const float4*)(Bw + (size_t)(n0 + a_r) * K + kb);

        __syncthreads();
        As[a_c + 0][a_r] = av.x; As[a_c + 1][a_r] = av.y;
        As[a_c + 2][a_r] = av.z; As[a_c + 3][a_r] = av.w;
        Bs[a_c + 0][a_r] = bv.x; Bs[a_c + 1][a_r] = bv.y;
        Bs[a_c + 2][a_r] = bv.z; Bs[a_c + 3][a_r] = bv.w;
        __syncthreads();

#pragma unroll
        for (int kk = 0; kk < 16; kk++) {
            float4 a  = *(const float4*)&As[kk][ty << 2];
            float4 bb = *(const float4*)&Bs[kk][tx << 2];
            float am[4] = {a.x, a.y, a.z, a.w};
            float bn[4] = {bb.x, bb.y, bb.z, bb.w};
#pragma unroll
            for (int i = 0; i < 4; i++)
#pragma unroll
                for (int j = 0; j < 4; j++)
                    acc[i][j] = fmaf(am[i], bn[j], acc[i][j]);
        }
    }

#pragma unroll
    for (int i = 0; i < 4; i++) {
        const int m = (ty << 2) + i;
#pragma unroll
        for (int j = 0; j < 4; j++) {
            const int n = n0 + (tx << 2) + j;
            C[(size_t)m * (3 * H_) + n] = acc[i][j];
        }
    }
}

// ---------------------------------------------------------------------------
// tf32 mma helpers.
// ---------------------------------------------------------------------------
__device__ __forceinline__ void cp_async16(void* dst, const void* src) {
    unsigned d = (unsigned)__cvta_generic_to_shared(dst);
    asm volatile("cp.async.ca.shared.global [%0], [%1], 16;" :: "r"(d), "l"(src));
}
__device__ __forceinline__ void cp_commit() {
    asm volatile("cp.async.commit_group;");
}
template <int N> __device__ __forceinline__ void cp_wait() {
    asm volatile("cp.async.wait_group %0;" :: "n"(N));
}
__device__ __forceinline__ unsigned f2tf(float x) {
    unsigned r;
    asm("cvt.rna.tf32.f32 %0, %1;" : "=r"(r) : "f"(x));
    return r;
}
__device__ __forceinline__ void mma_tf32(float4& c, const unsigned a[4],
                                         unsigned b0, unsigned b1) {
    asm volatile(
        "mma.sync.aligned.m16n8k8.row.col.f32.tf32.tf32.f32 "
        "{%0,%1,%2,%3}, {%4,%5,%6,%7}, {%8,%9}, {%0,%1,%2,%3};"
        : "+f"(c.x), "+f"(c.y), "+f"(c.z), "+f"(c.w)
        : "r"(a[0]), "r"(a[1]), "r"(a[2]), "r"(a[3]), "r"(b0), "r"(b1));
}

// ---------------------------------------------------------------------------
// Output GEMM v3 (unchanged): CTA tile 64x64, 4 warps 2x2, warp tile M32xN32,
// K-chunk 32, 2-stage cp.async, stride-36 smem.
// ---------------------------------------------------------------------------
#define OG_STRIDE 36
#define OG_TILE (64 * OG_STRIDE)
#define OG_SMEM (4 * OG_TILE * 4)

__global__ __launch_bounds__(128, 5) void out_gemm_v3(
    const float* __restrict__ A,    // [64, 1024]
    const float* __restrict__ Bw,   // [V, 1024]
    const float* __restrict__ bias, // [V]
    float* __restrict__ C)          // [64, V]
{
    extern __shared__ float smem[];
    float* Abuf = smem;
    float* Bbuf = smem + 2 * OG_TILE;

    const int tid = threadIdx.x;
    const int lane = tid & 31, warp = tid >> 5;
    const int wm = warp & 1, wn = warp >> 1;
    const int g = lane >> 2, tig = lane & 3;
    const int n_base = blockIdx.x * 64;

    const int lrow = tid >> 3;
    const int lcol = (tid & 7) * 4;

    float4 acc[2][4];
#pragma unroll
    for (int mf = 0; mf < 2; mf++)
#pragma unroll
        for (int j = 0; j < 4; j++) acc[mf][j] = make_float4(0.f, 0.f, 0.f, 0.f);

#define OG_STAGE(buf, ch) do {                                                  \
        float* Ad = Abuf + (buf) * OG_TILE;                                     \
        float* Bd = Bbuf + (buf) * OG_TILE;                                     \
        _Pragma("unroll")                                                       \
        for (int it = 0; it < 4; it++) {                                        \
            const int r = lrow + it * 16;                                       \
            cp_async16(Ad + r * OG_STRIDE + lcol,                               \
                       A + (size_t)r * 1024 + (ch) * 32 + lcol);                \
        }                                                                       \
        _Pragma("unroll")                                                       \
        for (int it = 0; it < 4; it++) {                                        \
            const int r = lrow + it * 16;                                       \
            if (n_base + r < V_)                                                \
                cp_async16(Bd + r * OG_STRIDE + lcol,                           \
                           Bw + (size_t)(n_base + r) * 1024 + (ch) * 32 + lcol);\
        }                                                                       \
        cp_commit();                                                            \
    } while (0)

    OG_STAGE(0, 0);

    for (int c = 0; c < 32; c++) {
        const int buf = c & 1;
        if (c < 31) { OG_STAGE(buf ^ 1, c + 1); cp_wait<1>(); }
        else        { cp_wait<0>(); }
        __syncthreads();

        const float* As_s = Abuf + buf * OG_TILE;
        const float* Bs_s = Bbuf + buf * OG_TILE;

#pragma unroll
        for (int ks4 = 0; ks4 < 4; ks4++) {
            const int k0i = ks4 * 8 + tig;
            const int k1i = k0i + 4;
            unsigned ua[2][4];
#pragma unroll
            for (int mf = 0; mf < 2; mf++) {
                const int m0 = wm * 32 + mf * 16;
                ua[mf][0] = f2tf(As_s[(m0 + g) * OG_STRIDE + k0i]);
                ua[mf][1] = f2tf(As_s[(m0 + g + 8) * OG_STRIDE + k0i]);
                ua[mf][2] = f2tf(As_s[(m0 + g) * OG_STRIDE + k1i]);
                ua[mf][3] = f2tf(As_s[(m0 + g + 8) * OG_STRIDE + k1i]);
            }
#pragma unroll
            for (int j = 0; j < 4; j++) {
                const int n0 = wn * 32 + j * 8;
                const unsigned b0 = f2tf(Bs_s[(n0 + g) * OG_STRIDE + k0i]);
                const unsigned b1 = f2tf(Bs_s[(n0 + g) * OG_STRIDE + k1i]);
#pragma unroll
                for (int mf = 0; mf < 2; mf++)
                    mma_tf32(acc[mf][j], ua[mf], b0, b1);
            }
        }
        __syncthreads();
    }
#undef OG_STAGE

#pragma unroll
    for (int mf = 0; mf < 2; mf++) {
        const int r0 = wm * 32 + mf * 16 + g;
#pragma unroll
        for (int j = 0; j < 4; j++) {
            const int col = n_base + wn * 32 + j * 8 + tig * 2;
            const float4 v = acc[mf][j];
            if (col + 1 < V_) {
                const float bv0 = bias[col], bv1 = bias[col + 1];
                C[(size_t)r0 * V_ + col]           = v.x + bv0;
                C[(size_t)r0 * V_ + col + 1]       = v.y + bv1;
                C[(size_t)(r0 + 8) * V_ + col]     = v.z + bv0;
                C[(size_t)(r0 + 8) * V_ + col + 1] = v.w + bv1;
            } else if (col < V_) {
                const float bv0 = bias[col];
                C[(size_t)r0 * V_ + col]       = v.x + bv0;
                C[(size_t)(r0 + 8) * V_ + col] = v.z + bv0;
            }
        }
    }
}

// ---------------------------------------------------------------------------
// GRU gate math (8 K-split partials).
// ---------------------------------------------------------------------------
__global__ void gru_gates(const float* __restrict__ b_ih,
                          const float* __restrict__ b_hh,
                          const float* __restrict__ hprev,
                          float* __restrict__ out_hidden)
{
    const int idx = blockIdx.x * blockDim.x + threadIdx.x;   // < B*H
    const int b = idx >> 10, h = idx & (H_ - 1);
    float gir = b_ih[h], giz = b_ih[H_ + h], gin = b_ih[2 * H_ + h];
    float ghr = b_hh[h], ghz = b_hh[H_ + h], ghn = b_hh[2 * H_ + h];
#pragma unroll
    for (int p = 0; p < 8; p++) {
        const float* gi = g_gi_part + (size_t)p * (B_ * 3 * H_) + (size_t)b * 3 * H_;
        const float* gh = g_gh_part + (size_t)p * (B_ * 3 * H_) + (size_t)b * 3 * H_;
        gir += gi[h];          ghr += gh[h];
        giz += gi[H_ + h];     ghz += gh[H_ + h];
        gin += gi[2 * H_ + h]; ghn += gh[2 * H_ + h];
    }
    const float r = 1.f / (1.f + expf(-(gir + ghr)));
    const float z = 1.f / (1.f + expf(-(giz + ghz)));
    const float n = tanhf(gin + r * ghn);
    const float hn = (1.f - z) * n + z * hprev[idx];
    g_concat_in[(size_t)b * 2 * H_ + h] = hn;
    out_hidden[idx] = hn;
}

// ---------------------------------------------------------------------------
// Flash-style attention (deferred rescale + in-CTA combine) — unchanged.
// ---------------------------------------------------------------------------
__global__ __launch_bounds__(256, 1) void flash_attn(const float* __restrict__ enc)
{
    const int b = blockIdx.y;
    const int chunk = blockIdx.x;
    __shared__ float sh[H_];
    __shared__ float stage[8][H_];
    __shared__ float red_m[8], red_l[8];
    const int t = threadIdx.x;
    *(float4*)&sh[t * 4] = *(const float4*)&g_concat_in[(size_t)b * 2 * H_ + t * 4];
    __syncthreads();

    const int warp = t >> 5, lane = t & 31;
    float4 hn[8];
#pragma unroll
    for (int i = 0; i < 8; i++) hn[i] = *(const float4*)&sh[i * 128 + lane * 4];

    float m = -INFINITY, l = 0.f;
    float4 cv[8];
#pragma unroll
    for (int i = 0; i < 8; i++) cv[i] = make_float4(0.f, 0.f, 0.f, 0.f);

    const int sbase = chunk * 128 + warp * 16;
    for (int si = 0; si < 16; si++) {
        const int s = sbase + si;
        const float4* ep = (const float4*)(enc + ((size_t)s * B_ + b) * H_);
        float4 ev[8];
        float d = 0.f;
#pragma unroll
        for (int i = 0; i < 8; i++) {
            ev[i] = ep[i * 32 + lane];
            d = fmaf(ev[i].x, hn[i].x, d);
            d = fmaf(ev[i].y, hn[i].y, d);
            d = fmaf(ev[i].z, hn[i].z, d);
            d = fmaf(ev[i].w, hn[i].w, d);
        }
#pragma unroll
        for (int off = 16; off; off >>= 1)
            d += __shfl_xor_sync(0xffffffffu, d, off);

        if (lane == 0) g_energies[(size_t)b * S_ + s] = d;

        if (d <= m) {
            const float p = expf(d - m);
            l += p;
#pragma unroll
            for (int i = 0; i < 8; i++) {
                cv[i].x = fmaf(p, ev[i].x, cv[i].x);
                cv[i].y = fmaf(p, ev[i].y, cv[i].y);
                cv[i].z = fmaf(p, ev[i].z, cv[i].z);
                cv[i].w = fmaf(p, ev[i].w, cv[i].w);
            }
        } else {
            const float sc = expf(m - d);
            l = fmaf(l, sc, 1.f);
#pragma unroll
            for (int i = 0; i < 8; i++) {
                cv[i].x = fmaf(cv[i].x, sc, ev[i].x);
                cv[i].y = fmaf(cv[i].y, sc, ev[i].y);
                cv[i].z = fmaf(cv[i].z, sc, ev[i].z);
                cv[i].w = fmaf(cv[i].w, sc, ev[i].w);
            }
            m = d;
        }
    }

    if (lane == 0) { red_m[warp] = m; red_l[warp] = l; }
    __syncthreads();
    float M = red_m[0];
#pragma unroll
    for (int i = 1; i < 8; i++) M = fmaxf(M, red_m[i]);
    float L = 0.f;
#pragma unroll
    for (int i = 0; i < 8; i++) L += red_l[i] * expf(red_m[i] - M);

    const float wsc = expf(m - M);
#pragma unroll
    for (int i = 0; i < 8; i++) {
        float4 v = cv[i];
        v.x *= wsc; v.y *= wsc; v.z *= wsc; v.w *= wsc;
        *(float4*)&stage[warp][i * 128 + lane * 4] = v;
    }
    __syncthreads();

    float4 acc = make_float4(0.f, 0.f, 0.f, 0.f);
#pragma unroll
    for (int w = 0; w < 8; w++) {
        const float4 v = *(const float4*)&stage[w][t * 4];
        acc.x += v.x; acc.y += v.y; acc.z += v.z; acc.w += v.w;
    }
    if (t == 0) g_ml[b * 16 + chunk] = make_float2(M, L);
    ((float4*)(g_ctxp + (size_t)(b * 16 + chunk) * H_))[t] = acc;
}

// ---------------------------------------------------------------------------
// Combine the 16 per-CTA softmax partials AND emit attention weights.
// ---------------------------------------------------------------------------
__global__ void attn_combine(float* __restrict__ out_attn)
{
    const int b = blockIdx.y, q = blockIdx.x, t = threadIdx.x;  // t < 64
    __shared__ float sm[16], sl[16];
    if (t < 16) { float2 ml = g_ml[b * 16 + t]; sm[t] = ml.x; sl[t] = ml.y; }
    __syncthreads();

    float M = sm[0];
#pragma unroll
    for (int i = 1; i < 16; i++) M = fmaxf(M, sm[i]);
    float L = 0.f;
#pragma unroll
    for (int i = 0; i < 16; i++) L += sl[i] * expf(sm[i] - M);
    const float inv = 1.f / L;

    float4 acc = make_float4(0.f, 0.f, 0.f, 0.f);
    const float4* base = (const float4*)(g_ctxp + (size_t)b * 16 * H_) + q * 64 + t;
#pragma unroll
    for (int p = 0; p < 16; p++) {
        const float f = expf(sm[p] - M);
        const float4 v = base[(size_t)p * (H_ / 4)];
        acc.x = fmaf(f, v.x, acc.x);
        acc.y = fmaf(f, v.y, acc.y);
        acc.z = fmaf(f, v.z, acc.z);
        acc.w = fmaf(f, v.w, acc.w);
    }
    acc.x *= inv; acc.y *= inv; acc.z *= inv; acc.w *= inv;
    *(float4*)&g_concat_in[(size_t)b * 2 * H_ + H_ + (q * 64 + t) * 4] = acc;

#pragma unroll
    for (int k = 0; k < 8; k++) {
        const int s = q * 512 + k * 64 + t;
        out_attn[(size_t)b * S_ + s] = expf(g_energies[(size_t)b * S_ + s] - M) * inv;
    }
}

// Sum concat-GEMM K-split partials (16), add bias, tanh.
__global__ void cat_finalize(const float* __restrict__ b_concat)
{
    const int idx = blockIdx.x * blockDim.x + threadIdx.x;   // < B*H
    float v = b_concat[idx & (H_ - 1)];
#pragma unroll
    for (int p = 0; p < 16; p++) v += g_cat_part[(size_t)p * (B_ * H_) + idx];
    g_concat_out[idx] = tanhf(v);
}

// ---------------------------------------------------------------------------
extern "C" void kernel_launch(void* const* d_in, const int* in_sizes, int n_in,
                              void* d_out, int out_size)
{
    (void)in_sizes; (void)n_in; (void)out_size;
    const float* x    = (const float*)d_in[0];
    const float* h0   = (const float*)d_in[1];
    const float* enc  = (const float*)d_in[2];
    const float* w_ih = (const float*)d_in[3];
    const float* w_hh = (const float*)d_in[4];
    const float* b_ih = (const float*)d_in[5];
    const float* b_hh = (const float*)d_in[6];
    const float* Wc   = (const float*)d_in[7];
    const float* bc   = (const float*)d_in[8];
    const float* Wo   = (const float*)d_in[9];
    const float* bo   = (const float*)d_in[10];

    float* out        = (float*)d_out;
    float* out_output = out;                              // [B,V]
    float* out_hidden = out + (size_t)B_ * V_;            // [1,B,H]
    float* out_attn   = out_hidden + (size_t)B_ * H_;     // [B,1,S]

    void *p_cat, *p_cin, *p_cout;
    cudaGetSymbolAddress(&p_cat, g_cat_part);
    cudaGetSymbolAddress(&p_cin, g_concat_in);
    cudaGetSymbolAddress(&p_cout, g_concat_out);

    cudaFuncSetAttribute(out_gemm_v3,
                         cudaFuncAttributeMaxDynamicSharedMemorySize, OG_SMEM);

    // idx 0: merged GRU GEMMs (768 CTAs, k-split x8 each)
    gemm_gru<<<dim3(48, 8, 2), 256>>>(x, h0, w_ih, w_hh);
    // idx 1: gate math
    gru_gates<<<(B_ * H_) / 256, 256>>>(b_ih, b_hh, h0, out_hidden);
    // idx 2: one-pass attention
    flash_attn<<<dim3(16, B_), 256>>>(enc);

    // idx 3 — DIAGNOSTIC (the slot ncu captures): full-size out_gemm_v3 on
    // the persistent g_concat_out scratch. Deterministic final output: the
    // real launch below overwrites every byte of out_output. Purpose:
    // first-ever profile of v3 + direct cost measurement (dur - base).
    out_gemm_v3<<<(V_ + 63) / 64, 128, OG_SMEM>>>((const float*)p_cout, Wo,
                                                  bo, out_output);

    // idx 4: combine + attention-weights output
    attn_combine<<<dim3(4, B_), 64>>>(out_attn);
    // idx 5: concat projection (k-split x16 -> 256 CTAs)
    gemm64<<<dim3(16, 16), 256>>>((const float*)p_cin, Wc, (float*)p_cat,
                                  H_, 2 * H_, 128, nullptr, 0);
    // idx 6: partial sum + bias + tanh
    cat_finalize<<<(B_ * H_) / 256, 256>>>(bc);

    // idx 7: REAL output GEMM
    out_gemm_v3<<<(V_ + 63) / 64, 128, OG_SMEM>>>((const float*)p_cout, Wo,
                                                  bo, out_output);
}

// round 16
// speedup vs baseline: 1.2055x; 1.2055x over previous
#include <cuda_runtime.h>
#include <math.h>

// Shapes (fixed by the problem)
#define B_ 64
#define S_ 2048
#define H_ 1024
#define E_ 512
#define V_ 50257

// ---------------------------------------------------------------------------
// Device scratch (allocation-free: __device__ globals).
// ---------------------------------------------------------------------------
__device__ float g_gi_part[8 * B_ * 3 * H_];      // 8 K-splits of x @ w_ih^T
__device__ float g_gh_part[8 * B_ * 3 * H_];      // 8 K-splits of h @ w_hh^T
__device__ float g_cat_part[16 * B_ * H_];        // 16 K-splits of concat GEMM
__device__ float g_concat_in[B_ * 2 * H_];
__device__ float g_concat_out[B_ * H_];           // tf32-pre-rounded tanh output
__device__ float g_energies[B_ * S_];
__device__ float2 g_ml[B_ * 16];
__device__ float g_ctxp[(size_t)B_ * 16 * H_];

// ---------------------------------------------------------------------------
// Generic small-GEMM (used for the concat projection).
// ---------------------------------------------------------------------------
__global__ __launch_bounds__(256) void gemm64(
    const float* __restrict__ A, const float* __restrict__ Bw,
    float* __restrict__ C, int N, int K, int klen,
    const float* __restrict__ bias, int act)
{
    __shared__ float As[16][64];
    __shared__ float Bs[16][64];
    const int tid = threadIdx.x;
    const int tx = tid & 15, ty = tid >> 4;
    const int n0 = blockIdx.x * 64;
    const int k0 = blockIdx.y * klen;
    C += (size_t)blockIdx.y * 64 * N;

    const int a_r = tid >> 2;
    const int a_c = (tid & 3) << 2;

    float acc[4][4];
#pragma unroll
    for (int i = 0; i < 4; i++)
#pragma unroll
        for (int j = 0; j < 4; j++) acc[i][j] = 0.f;

    for (int kk0 = 0; kk0 < klen; kk0 += 16) {
        const int kb = k0 + kk0 + a_c;
        float4 av = *(const float4*)(A + (size_t)a_r * K + kb);
        float4 bv = make_float4(0.f, 0.f, 0.f, 0.f);
        const int nr = n0 + a_r;
        if (nr < N) bv = *(const float4*)(Bw + (size_t)nr * K + kb);

        __syncthreads();
        As[a_c + 0][a_r] = av.x; As[a_c + 1][a_r] = av.y;
        As[a_c + 2][a_r] = av.z; As[a_c + 3][a_r] = av.w;
        Bs[a_c + 0][a_r] = bv.x; Bs[a_c + 1][a_r] = bv.y;
        Bs[a_c + 2][a_r] = bv.z; Bs[a_c + 3][a_r] = bv.w;
        __syncthreads();

#pragma unroll
        for (int kk = 0; kk < 16; kk++) {
            float4 a  = *(const float4*)&As[kk][ty << 2];
            float4 bb = *(const float4*)&Bs[kk][tx << 2];
            float am[4] = {a.x, a.y, a.z, a.w};
            float bn[4] = {bb.x, bb.y, bb.z, bb.w};
#pragma unroll
            for (int i = 0; i < 4; i++)
#pragma unroll
                for (int j = 0; j < 4; j++)
                    acc[i][j] = fmaf(am[i], bn[j], acc[i][j]);
        }
    }

#pragma unroll
    for (int i = 0; i < 4; i++) {
        const int m = (ty << 2) + i;
#pragma unroll
        for (int j = 0; j < 4; j++) {
            const int n = n0 + (tx << 2) + j;
            if (n < N) {
                float v = acc[i][j];
                if (bias) v += bias[n];
                if (act) v = tanhf(v);
                C[(size_t)m * N + n] = v;
            }
        }
    }
}

// ---------------------------------------------------------------------------
// Merged GRU GEMMs: ONE launch computes gi (z=0, K=512) and gh (z=1, K=1024),
// each 8-way K-split -> 768 CTAs.
// ---------------------------------------------------------------------------
__global__ __launch_bounds__(256) void gemm_gru(
    const float* __restrict__ x,    const float* __restrict__ h0,
    const float* __restrict__ w_ih, const float* __restrict__ w_hh)
{
    __shared__ float As[16][64];
    __shared__ float Bs[16][64];
    const int z = blockIdx.z;
    const float* A  = z ? h0   : x;
    const float* Bw = z ? w_hh : w_ih;
    float* C = (z ? g_gh_part : g_gi_part) + (size_t)blockIdx.y * 64 * 3 * H_;
    const int K = z ? 1024 : 512;
    const int klen = K >> 3;
    const int k0 = blockIdx.y * klen;
    const int n0 = blockIdx.x * 64;

    const int tid = threadIdx.x;
    const int tx = tid & 15, ty = tid >> 4;
    const int a_r = tid >> 2;
    const int a_c = (tid & 3) << 2;

    float acc[4][4];
#pragma unroll
    for (int i = 0; i < 4; i++)
#pragma unroll
        for (int j = 0; j < 4; j++) acc[i][j] = 0.f;

    for (int kk0 = 0; kk0 < klen; kk0 += 16) {
        const int kb = k0 + kk0 + a_c;
        float4 av = *(const float4*)(A + (size_t)a_r * K + kb);
        float4 bv = *(const float4*)(Bw + (size_t)(n0 + a_r) * K + kb);

        __syncthreads();
        As[a_c + 0][a_r] = av.x; As[a_c + 1][a_r] = av.y;
        As[a_c + 2][a_r] = av.z; As[a_c + 3][a_r] = av.w;
        Bs[a_c + 0][a_r] = bv.x; Bs[a_c + 1][a_r] = bv.y;
        Bs[a_c + 2][a_r] = bv.z; Bs[a_c + 3][a_r] = bv.w;
        __syncthreads();

#pragma unroll
        for (int kk = 0; kk < 16; kk++) {
            float4 a  = *(const float4*)&As[kk][ty << 2];
            float4 bb = *(const float4*)&Bs[kk][tx << 2];
            float am[4] = {a.x, a.y, a.z, a.w};
            float bn[4] = {bb.x, bb.y, bb.z, bb.w};
#pragma unroll
            for (int i = 0; i < 4; i++)
#pragma unroll
                for (int j = 0; j < 4; j++)
                    acc[i][j] = fmaf(am[i], bn[j], acc[i][j]);
        }
    }

#pragma unroll
    for (int i = 0; i < 4; i++) {
        const int m = (ty << 2) + i;
#pragma unroll
        for (int j = 0; j < 4; j++) {
            const int n = n0 + (tx << 2) + j;
            C[(size_t)m * (3 * H_) + n] = acc[i][j];
        }
    }
}

// ---------------------------------------------------------------------------
// tf32 mma helpers.
// ---------------------------------------------------------------------------
__device__ __forceinline__ void cp_async16(void* dst, const void* src) {
    unsigned d = (unsigned)__cvta_generic_to_shared(dst);
    asm volatile("cp.async.ca.shared.global [%0], [%1], 16;" :: "r"(d), "l"(src));
}
__device__ __forceinline__ void cp_commit() {
    asm volatile("cp.async.commit_group;");
}
template <int N> __device__ __forceinline__ void cp_wait() {
    asm volatile("cp.async.wait_group %0;" :: "n"(N));
}
__device__ __forceinline__ unsigned f2tf(float x) {
    unsigned r;
    asm("cvt.rna.tf32.f32 %0, %1;" : "=r"(r) : "f"(x));
    return r;
}
__device__ __forceinline__ void mma_tf32(float4& c, const unsigned a[4],
                                         unsigned b0, unsigned b1) {
    asm volatile(
        "mma.sync.aligned.m16n8k8.row.col.f32.tf32.tf32.f32 "
        "{%0,%1,%2,%3}, {%4,%5,%6,%7}, {%8,%9}, {%0,%1,%2,%3};"
        : "+f"(c.x), "+f"(c.y), "+f"(c.z), "+f"(c.w)
        : "r"(a[0]), "r"(a[1]), "r"(a[2]), "r"(a[3]), "r"(b0), "r"(b1));
}

// ---------------------------------------------------------------------------
// Output GEMM v4: CTA tile 64x64, 4 warps 2x2, warp tile M32xN32, K-chunk 32,
// 2-stage cp.async, stride-36 smem.
// v4 changes vs v3 (profiled: L1 59% / issue 44% bound):
//  - pair-k fragment permutation: mma k-slots (tig, tig+4) are fed actual
//    k = (2*tig, 2*tig+1) for BOTH A and B (dot over k is permutation-
//    invariant) -> each thread's two k-values are adjacent -> float2 LDS.
//    Halves LDS instruction count (same bytes).
//  - A arrives pre-rounded to tf32 (cat_finalize) -> A-side CVTs removed.
// ---------------------------------------------------------------------------
#define OG_STRIDE 36
#define OG_TILE (64 * OG_STRIDE)
#define OG_SMEM (4 * OG_TILE * 4)

__global__ __launch_bounds__(128, 5) void out_gemm_v4(
    const float* __restrict__ A,    // [64, 1024] tf32-pre-rounded
    const float* __restrict__ Bw,   // [V, 1024]
    const float* __restrict__ bias, // [V]
    float* __restrict__ C)          // [64, V]
{
    extern __shared__ float smem[];
    float* Abuf = smem;
    float* Bbuf = smem + 2 * OG_TILE;

    const int tid = threadIdx.x;
    const int lane = tid & 31, warp = tid >> 5;
    const int wm = warp & 1, wn = warp >> 1;
    const int g = lane >> 2, tig = lane & 3;
    const int n_base = blockIdx.x * 64;

    const int lrow = tid >> 3;
    const int lcol = (tid & 7) * 4;

    float4 acc[2][4];
#pragma unroll
    for (int mf = 0; mf < 2; mf++)
#pragma unroll
        for (int j = 0; j < 4; j++) acc[mf][j] = make_float4(0.f, 0.f, 0.f, 0.f);

#define OG_STAGE(buf, ch) do {                                                  \
        float* Ad = Abuf + (buf) * OG_TILE;                                     \
        float* Bd = Bbuf + (buf) * OG_TILE;                                     \
        _Pragma("unroll")                                                       \
        for (int it = 0; it < 4; it++) {                                        \
            const int r = lrow + it * 16;                                       \
            cp_async16(Ad + r * OG_STRIDE + lcol,                               \
                       A + (size_t)r * 1024 + (ch) * 32 + lcol);                \
        }                                                                       \
        _Pragma("unroll")                                                       \
        for (int it = 0; it < 4; it++) {                                        \
            const int r = lrow + it * 16;                                       \
            if (n_base + r < V_)                                                \
                cp_async16(Bd + r * OG_STRIDE + lcol,                           \
                           Bw + (size_t)(n_base + r) * 1024 + (ch) * 32 + lcol);\
        }                                                                       \
        cp_commit();                                                            \
    } while (0)

    OG_STAGE(0, 0);

    for (int c = 0; c < 32; c++) {
        const int buf = c & 1;
        if (c < 31) { OG_STAGE(buf ^ 1, c + 1); cp_wait<1>(); }
        else        { cp_wait<0>(); }
        __syncthreads();

        const float* As_s = Abuf + buf * OG_TILE;
        const float* Bs_s = Bbuf + buf * OG_TILE;

#pragma unroll
        for (int ks4 = 0; ks4 < 4; ks4++) {
            const int k0i = ks4 * 8 + tig * 2;       // even -> 8B aligned
            unsigned ua[2][4];
#pragma unroll
            for (int mf = 0; mf < 2; mf++) {
                const int m0 = wm * 32 + mf * 16;
                const float2 a0 = *(const float2*)&As_s[(m0 + g) * OG_STRIDE + k0i];
                const float2 a1 = *(const float2*)&As_s[(m0 + g + 8) * OG_STRIDE + k0i];
                ua[mf][0] = __float_as_uint(a0.x);   // slot k=tig
                ua[mf][1] = __float_as_uint(a1.x);
                ua[mf][2] = __float_as_uint(a0.y);   // slot k=tig+4
                ua[mf][3] = __float_as_uint(a1.y);
            }
#pragma unroll
            for (int j = 0; j < 4; j++) {
                const int n0 = wn * 32 + j * 8;
                const float2 bb = *(const float2*)&Bs_s[(n0 + g) * OG_STRIDE + k0i];
                const unsigned b0 = f2tf(bb.x);
                const unsigned b1 = f2tf(bb.y);
#pragma unroll
                for (int mf = 0; mf < 2; mf++)
                    mma_tf32(acc[mf][j], ua[mf], b0, b1);
            }
        }
        __syncthreads();
    }
#undef OG_STAGE

#pragma unroll
    for (int mf = 0; mf < 2; mf++) {
        const int r0 = wm * 32 + mf * 16 + g;
#pragma unroll
        for (int j = 0; j < 4; j++) {
            const int col = n_base + wn * 32 + j * 8 + tig * 2;
            const float4 v = acc[mf][j];
            if (col + 1 < V_) {
                const float bv0 = bias[col], bv1 = bias[col + 1];
                C[(size_t)r0 * V_ + col]           = v.x + bv0;
                C[(size_t)r0 * V_ + col + 1]       = v.y + bv1;
                C[(size_t)(r0 + 8) * V_ + col]     = v.z + bv0;
                C[(size_t)(r0 + 8) * V_ + col + 1] = v.w + bv1;
            } else if (col < V_) {
                const float bv0 = bias[col];
                C[(size_t)r0 * V_ + col]       = v.x + bv0;
                C[(size_t)(r0 + 8) * V_ + col] = v.z + bv0;
            }
        }
    }
}

// ---------------------------------------------------------------------------
// GRU gate math (8 K-split partials).
// ---------------------------------------------------------------------------
__global__ void gru_gates(const float* __restrict__ b_ih,
                          const float* __restrict__ b_hh,
                          const float* __restrict__ hprev,
                          float* __restrict__ out_hidden)
{
    const int idx = blockIdx.x * blockDim.x + threadIdx.x;   // < B*H
    const int b = idx >> 10, h = idx & (H_ - 1);
    float gir = b_ih[h], giz = b_ih[H_ + h], gin = b_ih[2 * H_ + h];
    float ghr = b_hh[h], ghz = b_hh[H_ + h], ghn = b_hh[2 * H_ + h];
#pragma unroll
    for (int p = 0; p < 8; p++) {
        const float* gi = g_gi_part + (size_t)p * (B_ * 3 * H_) + (size_t)b * 3 * H_;
        const float* gh = g_gh_part + (size_t)p * (B_ * 3 * H_) + (size_t)b * 3 * H_;
        gir += gi[h];          ghr += gh[h];
        giz += gi[H_ + h];     ghz += gh[H_ + h];
        gin += gi[2 * H_ + h]; ghn += gh[2 * H_ + h];
    }
    const float r = 1.f / (1.f + expf(-(gir + ghr)));
    const float z = 1.f / (1.f + expf(-(giz + ghz)));
    const float n = tanhf(gin + r * ghn);
    const float hn = (1.f - z) * n + z * hprev[idx];
    g_concat_in[(size_t)b * 2 * H_ + h] = hn;
    out_hidden[idx] = hn;
}

// ---------------------------------------------------------------------------
// Flash-style attention (deferred rescale + in-CTA combine) — unchanged.
// ---------------------------------------------------------------------------
__global__ __launch_bounds__(256, 1) void flash_attn(const float* __restrict__ enc)
{
    const int b = blockIdx.y;
    const int chunk = blockIdx.x;
    __shared__ float sh[H_];
    __shared__ float stage[8][H_];
    __shared__ float red_m[8], red_l[8];
    const int t = threadIdx.x;
    *(float4*)&sh[t * 4] = *(const float4*)&g_concat_in[(size_t)b * 2 * H_ + t * 4];
    __syncthreads();

    const int warp = t >> 5, lane = t & 31;
    float4 hn[8];
#pragma unroll
    for (int i = 0; i < 8; i++) hn[i] = *(const float4*)&sh[i * 128 + lane * 4];

    float m = -INFINITY, l = 0.f;
    float4 cv[8];
#pragma unroll
    for (int i = 0; i < 8; i++) cv[i] = make_float4(0.f, 0.f, 0.f, 0.f);

    const int sbase = chunk * 128 + warp * 16;
    for (int si = 0; si < 16; si++) {
        const int s = sbase + si;
        const float4* ep = (const float4*)(enc + ((size_t)s * B_ + b) * H_);
        float4 ev[8];
        float d = 0.f;
#pragma unroll
        for (int i = 0; i < 8; i++) {
            ev[i] = ep[i * 32 + lane];
            d = fmaf(ev[i].x, hn[i].x, d);
            d = fmaf(ev[i].y, hn[i].y, d);
            d = fmaf(ev[i].z, hn[i].z, d);
            d = fmaf(ev[i].w, hn[i].w, d);
        }
#pragma unroll
        for (int off = 16; off; off >>= 1)
            d += __shfl_xor_sync(0xffffffffu, d, off);

        if (lane == 0) g_energies[(size_t)b * S_ + s] = d;

        if (d <= m) {
            const float p = expf(d - m);
            l += p;
#pragma unroll
            for (int i = 0; i < 8; i++) {
                cv[i].x = fmaf(p, ev[i].x, cv[i].x);
                cv[i].y = fmaf(p, ev[i].y, cv[i].y);
                cv[i].z = fmaf(p, ev[i].z, cv[i].z);
                cv[i].w = fmaf(p, ev[i].w, cv[i].w);
            }
        } else {
            const float sc = expf(m - d);
            l = fmaf(l, sc, 1.f);
#pragma unroll
            for (int i = 0; i < 8; i++) {
                cv[i].x = fmaf(cv[i].x, sc, ev[i].x);
                cv[i].y = fmaf(cv[i].y, sc, ev[i].y);
                cv[i].z = fmaf(cv[i].z, sc, ev[i].z);
                cv[i].w = fmaf(cv[i].w, sc, ev[i].w);
            }
            m = d;
        }
    }

    if (lane == 0) { red_m[warp] = m; red_l[warp] = l; }
    __syncthreads();
    float M = red_m[0];
#pragma unroll
    for (int i = 1; i < 8; i++) M = fmaxf(M, red_m[i]);
    float L = 0.f;
#pragma unroll
    for (int i = 0; i < 8; i++) L += red_l[i] * expf(red_m[i] - M);

    const float wsc = expf(m - M);
#pragma unroll
    for (int i = 0; i < 8; i++) {
        float4 v = cv[i];
        v.x *= wsc; v.y *= wsc; v.z *= wsc; v.w *= wsc;
        *(float4*)&stage[warp][i * 128 + lane * 4] = v;
    }
    __syncthreads();

    float4 acc = make_float4(0.f, 0.f, 0.f, 0.f);
#pragma unroll
    for (int w = 0; w < 8; w++) {
        const float4 v = *(const float4*)&stage[w][t * 4];
        acc.x += v.x; acc.y += v.y; acc.z += v.z; acc.w += v.w;
    }
    if (t == 0) g_ml[b * 16 + chunk] = make_float2(M, L);
    ((float4*)(g_ctxp + (size_t)(b * 16 + chunk) * H_))[t] = acc;
}

// ---------------------------------------------------------------------------
// Combine the 16 per-CTA softmax partials AND emit attention weights.
// ---------------------------------------------------------------------------
__global__ void attn_combine(float* __restrict__ out_attn)
{
    const int b = blockIdx.y, q = blockIdx.x, t = threadIdx.x;  // t < 64
    __shared__ float sm[16], sl[16];
    if (t < 16) { float2 ml = g_ml[b * 16 + t]; sm[t] = ml.x; sl[t] = ml.y; }
    __syncthreads();

    float M = sm[0];
#pragma unroll
    for (int i = 1; i < 16; i++) M = fmaxf(M, sm[i]);
    float L = 0.f;
#pragma unroll
    for (int i = 0; i < 16; i++) L += sl[i] * expf(sm[i] - M);
    const float inv = 1.f / L;

    float4 acc = make_float4(0.f, 0.f, 0.f, 0.f);
    const float4* base = (const float4*)(g_ctxp + (size_t)b * 16 * H_) + q * 64 + t;
#pragma unroll
    for (int p = 0; p < 16; p++) {
        const float f = expf(sm[p] - M);
        const float4 v = base[(size_t)p * (H_ / 4)];
        acc.x = fmaf(f, v.x, acc.x);
        acc.y = fmaf(f, v.y, acc.y);
        acc.z = fmaf(f, v.z, acc.z);
        acc.w = fmaf(f, v.w, acc.w);
    }
    acc.x *= inv; acc.y *= inv; acc.z *= inv; acc.w *= inv;
    *(float4*)&g_concat_in[(size_t)b * 2 * H_ + H_ + (q * 64 + t) * 4] = acc;

#pragma unroll
    for (int k = 0; k < 8; k++) {
        const int s = q * 512 + k * 64 + t;
        out_attn[(size_t)b * S_ + s] = expf(g_energies[(size_t)b * S_ + s] - M) * inv;
    }
}

// Sum concat-GEMM K-split partials (16), add bias, tanh, pre-round to tf32
// (exactly the value out_gemm's A-side CVT would have produced).
__global__ void cat_finalize(const float* __restrict__ b_concat)
{
    const int idx = blockIdx.x * blockDim.x + threadIdx.x;   // < B*H
    float v = b_concat[idx & (H_ - 1)];
#pragma unroll
    for (int p = 0; p < 16; p++) v += g_cat_part[(size_t)p * (B_ * H_) + idx];
    g_concat_out[idx] = __uint_as_float(f2tf(tanhf(v)));
}

// ---------------------------------------------------------------------------
extern "C" void kernel_launch(void* const* d_in, const int* in_sizes, int n_in,
                              void* d_out, int out_size)
{
    (void)in_sizes; (void)n_in; (void)out_size;
    const float* x    = (const float*)d_in[0];
    const float* h0   = (const float*)d_in[1];
    const float* enc  = (const float*)d_in[2];
    const float* w_ih = (const float*)d_in[3];
    const float* w_hh = (const float*)d_in[4];
    const float* b_ih = (const float*)d_in[5];
    const float* b_hh = (const float*)d_in[6];
    const float* Wc   = (const float*)d_in[7];
    const float* bc   = (const float*)d_in[8];
    const float* Wo   = (const float*)d_in[9];
    const float* bo   = (const float*)d_in[10];

    float* out        = (float*)d_out;
    float* out_output = out;                              // [B,V]
    float* out_hidden = out + (size_t)B_ * V_;            // [1,B,H]
    float* out_attn   = out_hidden + (size_t)B_ * H_;     // [B,1,S]

    void *p_cat, *p_cin, *p_cout;
    cudaGetSymbolAddress(&p_cat, g_cat_part);
    cudaGetSymbolAddress(&p_cin, g_concat_in);
    cudaGetSymbolAddress(&p_cout, g_concat_out);

    cudaFuncSetAttribute(out_gemm_v4,
                         cudaFuncAttributeMaxDynamicSharedMemorySize, OG_SMEM);

    // merged GRU GEMMs (768 CTAs, k-split x8 each)
    gemm_gru<<<dim3(48, 8, 2), 256>>>(x, h0, w_ih, w_hh);
    gru_gates<<<(B_ * H_) / 256, 256>>>(b_ih, b_hh, h0, out_hidden);

    // one-pass attention + fused combine/attn-weights
    flash_attn<<<dim3(16, B_), 256>>>(enc);
    attn_combine<<<dim3(4, B_), 64>>>(out_attn);

    // concat projection (k-split x16 -> 256 CTAs) + finalize (tf32 pre-round)
    gemm64<<<dim3(16, 16), 256>>>((const float*)p_cin, Wc, (float*)p_cat,
                                  H_, 2 * H_, 128, nullptr, 0);
    cat_finalize<<<(B_ * H_) / 256, 256>>>(bc);

    // Output GEMM: 64 x 50257 x 1024 (+bias), tf32 v4, 786 CTAs
    out_gemm_v4<<<(V_ + 63) / 64, 128, OG_SMEM>>>((const float*)p_cout, Wo,
                                                  bo, out_output);
}

// round 17
// speedup vs baseline: 1.2555x; 1.0415x over previous
#include <cuda_runtime.h>
#include <math.h>

// Shapes (fixed by the problem)
#define B_ 64
#define S_ 2048
#define H_ 1024
#define E_ 512
#define V_ 50257

// ---------------------------------------------------------------------------
// Device scratch (allocation-free: __device__ globals).
// ---------------------------------------------------------------------------
__device__ float g_gi_part[8 * B_ * 3 * H_];      // 8 K-splits of x @ w_ih^T
__device__ float g_gh_part[8 * B_ * 3 * H_];      // 8 K-splits of h @ w_hh^T
__device__ float g_cat_part[16 * B_ * H_];        // 16 K-splits of concat GEMM
__device__ float g_concat_in[B_ * 2 * H_];
__device__ float g_concat_out[B_ * H_];           // tf32-pre-rounded tanh output
__device__ float g_energies[B_ * S_];
__device__ float2 g_ml[B_ * 16];
__device__ float g_ctxp[(size_t)B_ * 16 * H_];

// ---------------------------------------------------------------------------
// Generic small-GEMM (used for the concat projection).
// ---------------------------------------------------------------------------
__global__ __launch_bounds__(256) void gemm64(
    const float* __restrict__ A, const float* __restrict__ Bw,
    float* __restrict__ C, int N, int K, int klen,
    const float* __restrict__ bias, int act)
{
    __shared__ float As[16][64];
    __shared__ float Bs[16][64];
    const int tid = threadIdx.x;
    const int tx = tid & 15, ty = tid >> 4;
    const int n0 = blockIdx.x * 64;
    const int k0 = blockIdx.y * klen;
    C += (size_t)blockIdx.y * 64 * N;

    const int a_r = tid >> 2;
    const int a_c = (tid & 3) << 2;

    float acc[4][4];
#pragma unroll
    for (int i = 0; i < 4; i++)
#pragma unroll
        for (int j = 0; j < 4; j++) acc[i][j] = 0.f;

    for (int kk0 = 0; kk0 < klen; kk0 += 16) {
        const int kb = k0 + kk0 + a_c;
        float4 av = *(const float4*)(A + (size_t)a_r * K + kb);
        float4 bv = make_float4(0.f, 0.f, 0.f, 0.f);
        const int nr = n0 + a_r;
        if (nr < N) bv = *(const float4*)(Bw + (size_t)nr * K + kb);

        __syncthreads();
        As[a_c + 0][a_r] = av.x; As[a_c + 1][a_r] = av.y;
        As[a_c + 2][a_r] = av.z; As[a_c + 3][a_r] = av.w;
        Bs[a_c + 0][a_r] = bv.x; Bs[a_c + 1][a_r] = bv.y;
        Bs[a_c + 2][a_r] = bv.z; Bs[a_c + 3][a_r] = bv.w;
        __syncthreads();

#pragma unroll
        for (int kk = 0; kk < 16; kk++) {
            float4 a  = *(const float4*)&As[kk][ty << 2];
            float4 bb = *(const float4*)&Bs[kk][tx << 2];
            float am[4] = {a.x, a.y, a.z, a.w};
            float bn[4] = {bb.x, bb.y, bb.z, bb.w};
#pragma unroll
            for (int i = 0; i < 4; i++)
#pragma unroll
                for (int j = 0; j < 4; j++)
                    acc[i][j] = fmaf(am[i], bn[j], acc[i][j]);
        }
    }

#pragma unroll
    for (int i = 0; i < 4; i++) {
        const int m = (ty << 2) + i;
#pragma unroll
        for (int j = 0; j < 4; j++) {
            const int n = n0 + (tx << 2) + j;
            if (n < N) {
                float v = acc[i][j];
                if (bias) v += bias[n];
                if (act) v = tanhf(v);
                C[(size_t)m * N + n] = v;
            }
        }
    }
}

// ---------------------------------------------------------------------------
// Merged GRU GEMMs: ONE launch computes gi (z=0, K=512) and gh (z=1, K=1024),
// each 8-way K-split -> 768 CTAs.
// ---------------------------------------------------------------------------
__global__ __launch_bounds__(256) void gemm_gru(
    const float* __restrict__ x,    const float* __restrict__ h0,
    const float* __restrict__ w_ih, const float* __restrict__ w_hh)
{
    __shared__ float As[16][64];
    __shared__ float Bs[16][64];
    const int z = blockIdx.z;
    const float* A  = z ? h0   : x;
    const float* Bw = z ? w_hh : w_ih;
    float* C = (z ? g_gh_part : g_gi_part) + (size_t)blockIdx.y * 64 * 3 * H_;
    const int K = z ? 1024 : 512;
    const int klen = K >> 3;
    const int k0 = blockIdx.y * klen;
    const int n0 = blockIdx.x * 64;

    const int tid = threadIdx.x;
    const int tx = tid & 15, ty = tid >> 4;
    const int a_r = tid >> 2;
    const int a_c = (tid & 3) << 2;

    float acc[4][4];
#pragma unroll
    for (int i = 0; i < 4; i++)
#pragma unroll
        for (int j = 0; j < 4; j++) acc[i][j] = 0.f;

    for (int kk0 = 0; kk0 < klen; kk0 += 16) {
        const int kb = k0 + kk0 + a_c;
        float4 av = *(const float4*)(A + (size_t)a_r * K + kb);
        float4 bv = *(const float4*)(Bw + (size_t)(n0 + a_r) * K + kb);

        __syncthreads();
        As[a_c + 0][a_r] = av.x; As[a_c + 1][a_r] = av.y;
        As[a_c + 2][a_r] = av.z; As[a_c + 3][a_r] = av.w;
        Bs[a_c + 0][a_r] = bv.x; Bs[a_c + 1][a_r] = bv.y;
        Bs[a_c + 2][a_r] = bv.z; Bs[a_c + 3][a_r] = bv.w;
        __syncthreads();

#pragma unroll
        for (int kk = 0; kk < 16; kk++) {
            float4 a  = *(const float4*)&As[kk][ty << 2];
            float4 bb = *(const float4*)&Bs[kk][tx << 2];
            float am[4] = {a.x, a.y, a.z, a.w};
            float bn[4] = {bb.x, bb.y, bb.z, bb.w};
#pragma unroll
            for (int i = 0; i < 4; i++)
#pragma unroll
                for (int j = 0; j < 4; j++)
                    acc[i][j] = fmaf(am[i], bn[j], acc[i][j]);
        }
    }

#pragma unroll
    for (int i = 0; i < 4; i++) {
        const int m = (ty << 2) + i;
#pragma unroll
        for (int j = 0; j < 4; j++) {
            const int n = n0 + (tx << 2) + j;
            C[(size_t)m * (3 * H_) + n] = acc[i][j];
        }
    }
}

// ---------------------------------------------------------------------------
// tf32 mma helpers.
// ---------------------------------------------------------------------------
__device__ __forceinline__ void cp_async16(void* dst, const void* src) {
    unsigned d = (unsigned)__cvta_generic_to_shared(dst);
    asm volatile("cp.async.ca.shared.global [%0], [%1], 16;" :: "r"(d), "l"(src));
}
__device__ __forceinline__ void cp_commit() {
    asm volatile("cp.async.commit_group;");
}
template <int N> __device__ __forceinline__ void cp_wait() {
    asm volatile("cp.async.wait_group %0;" :: "n"(N));
}
__device__ __forceinline__ unsigned f2tf(float x) {
    unsigned r;
    asm("cvt.rna.tf32.f32 %0, %1;" : "=r"(r) : "f"(x));
    return r;
}
__device__ __forceinline__ void mma_tf32(float4& c, const unsigned a[4],
                                         unsigned b0, unsigned b1) {
    asm volatile(
        "mma.sync.aligned.m16n8k8.row.col.f32.tf32.tf32.f32 "
        "{%0,%1,%2,%3}, {%4,%5,%6,%7}, {%8,%9}, {%0,%1,%2,%3};"
        : "+f"(c.x), "+f"(c.y), "+f"(c.z), "+f"(c.w)
        : "r"(a[0]), "r"(a[1]), "r"(a[2]), "r"(a[3]), "r"(b0), "r"(b1));
}

// ---------------------------------------------------------------------------
// Output GEMM v4b: CTA tile 64x64, 4 warps 2x2, warp tile M32xN32, K-chunk 32,
// 2-stage cp.async.
// Stride 40 (vs v4's 36): float2 fragment loads hit bank-pair
// (20g + tig) mod 16 = (4g + tig) mod 16 -> all 16 distinct per phase,
// CONFLICT-FREE (v4's stride 36 gave (2g+tig) mod 16 -> 2-way conflicts,
// which is why it regressed). Pair-k permutation + pre-rounded A kept:
// per-element rounding and accumulation order unchanged.
// smem = 4 * 64*40 * 4B = 40960 B -> 5 CTAs/SM.
// ---------------------------------------------------------------------------
#define OG_STRIDE 40
#define OG_TILE (64 * OG_STRIDE)
#define OG_SMEM (4 * OG_TILE * 4)

__global__ __launch_bounds__(128, 5) void out_gemm_v4(
    const float* __restrict__ A,    // [64, 1024] tf32-pre-rounded
    const float* __restrict__ Bw,   // [V, 1024]
    const float* __restrict__ bias, // [V]
    float* __restrict__ C)          // [64, V]
{
    extern __shared__ float smem[];
    float* Abuf = smem;
    float* Bbuf = smem + 2 * OG_TILE;

    const int tid = threadIdx.x;
    const int lane = tid & 31, warp = tid >> 5;
    const int wm = warp & 1, wn = warp >> 1;
    const int g = lane >> 2, tig = lane & 3;
    const int n_base = blockIdx.x * 64;

    const int lrow = tid >> 3;
    const int lcol = (tid & 7) * 4;

    float4 acc[2][4];
#pragma unroll
    for (int mf = 0; mf < 2; mf++)
#pragma unroll
        for (int j = 0; j < 4; j++) acc[mf][j] = make_float4(0.f, 0.f, 0.f, 0.f);

#define OG_STAGE(buf, ch) do {                                                  \
        float* Ad = Abuf + (buf) * OG_TILE;                                     \
        float* Bd = Bbuf + (buf) * OG_TILE;                                     \
        _Pragma("unroll")                                                       \
        for (int it = 0; it < 4; it++) {                                        \
            const int r = lrow + it * 16;                                       \
            cp_async16(Ad + r * OG_STRIDE + lcol,                               \
                       A + (size_t)r * 1024 + (ch) * 32 + lcol);                \
        }                                                                       \
        _Pragma("unroll")                                                       \
        for (int it = 0; it < 4; it++) {                                        \
            const int r = lrow + it * 16;                                       \
            if (n_base + r < V_)                                                \
                cp_async16(Bd + r * OG_STRIDE + lcol,                           \
                           Bw + (size_t)(n_base + r) * 1024 + (ch) * 32 + lcol);\
        }                                                                       \
        cp_commit();                                                            \
    } while (0)

    OG_STAGE(0, 0);

    for (int c = 0; c < 32; c++) {
        const int buf = c & 1;
        if (c < 31) { OG_STAGE(buf ^ 1, c + 1); cp_wait<1>(); }
        else        { cp_wait<0>(); }
        __syncthreads();

        const float* As_s = Abuf + buf * OG_TILE;
        const float* Bs_s = Bbuf + buf * OG_TILE;

#pragma unroll
        for (int ks4 = 0; ks4 < 4; ks4++) {
            const int k0i = ks4 * 8 + tig * 2;       // even -> 8B aligned
            unsigned ua[2][4];
#pragma unroll
            for (int mf = 0; mf < 2; mf++) {
                const int m0 = wm * 32 + mf * 16;
                const float2 a0 = *(const float2*)&As_s[(m0 + g) * OG_STRIDE + k0i];
                const float2 a1 = *(const float2*)&As_s[(m0 + g + 8) * OG_STRIDE + k0i];
                ua[mf][0] = __float_as_uint(a0.x);   // slot k=tig
                ua[mf][1] = __float_as_uint(a1.x);
                ua[mf][2] = __float_as_uint(a0.y);   // slot k=tig+4
                ua[mf][3] = __float_as_uint(a1.y);
            }
#pragma unroll
            for (int j = 0; j < 4; j++) {
                const int n0 = wn * 32 + j * 8;
                const float2 bb = *(const float2*)&Bs_s[(n0 + g) * OG_STRIDE + k0i];
                const unsigned b0 = f2tf(bb.x);
                const unsigned b1 = f2tf(bb.y);
#pragma unroll
                for (int mf = 0; mf < 2; mf++)
                    mma_tf32(acc[mf][j], ua[mf], b0, b1);
            }
        }
        __syncthreads();
    }
#undef OG_STAGE

#pragma unroll
    for (int mf = 0; mf < 2; mf++) {
        const int r0 = wm * 32 + mf * 16 + g;
#pragma unroll
        for (int j = 0; j < 4; j++) {
            const int col = n_base + wn * 32 + j * 8 + tig * 2;
            const float4 v = acc[mf][j];
            if (col + 1 < V_) {
                const float bv0 = bias[col], bv1 = bias[col + 1];
                C[(size_t)r0 * V_ + col]           = v.x + bv0;
                C[(size_t)r0 * V_ + col + 1]       = v.y + bv1;
                C[(size_t)(r0 + 8) * V_ + col]     = v.z + bv0;
                C[(size_t)(r0 + 8) * V_ + col + 1] = v.w + bv1;
            } else if (col < V_) {
                const float bv0 = bias[col];
                C[(size_t)r0 * V_ + col]       = v.x + bv0;
                C[(size_t)(r0 + 8) * V_ + col] = v.z + bv0;
            }
        }
    }
}

// ---------------------------------------------------------------------------
// GRU gate math (8 K-split partials).
// ---------------------------------------------------------------------------
__global__ void gru_gates(const float* __restrict__ b_ih,
                          const float* __restrict__ b_hh,
                          const float* __restrict__ hprev,
                          float* __restrict__ out_hidden)
{
    const int idx = blockIdx.x * blockDim.x + threadIdx.x;   // < B*H
    const int b = idx >> 10, h = idx & (H_ - 1);
    float gir = b_ih[h], giz = b_ih[H_ + h], gin = b_ih[2 * H_ + h];
    float ghr = b_hh[h], ghz = b_hh[H_ + h], ghn = b_hh[2 * H_ + h];
#pragma unroll
    for (int p = 0; p < 8; p++) {
        const float* gi = g_gi_part + (size_t)p * (B_ * 3 * H_) + (size_t)b * 3 * H_;
        const float* gh = g_gh_part + (size_t)p * (B_ * 3 * H_) + (size_t)b * 3 * H_;
        gir += gi[h];          ghr += gh[h];
        giz += gi[H_ + h];     ghz += gh[H_ + h];
        gin += gi[2 * H_ + h]; ghn += gh[2 * H_ + h];
    }
    const float r = 1.f / (1.f + expf(-(gir + ghr)));
    const float z = 1.f / (1.f + expf(-(giz + ghz)));
    const float n = tanhf(gin + r * ghn);
    const float hn = (1.f - z) * n + z * hprev[idx];
    g_concat_in[(size_t)b * 2 * H_ + h] = hn;
    out_hidden[idx] = hn;
}

// ---------------------------------------------------------------------------
// Flash-style attention (deferred rescale + in-CTA combine) — unchanged.
// ---------------------------------------------------------------------------
__global__ __launch_bounds__(256, 1) void flash_attn(const float* __restrict__ enc)
{
    const int b = blockIdx.y;
    const int chunk = blockIdx.x;
    __shared__ float sh[H_];
    __shared__ float stage[8][H_];
    __shared__ float red_m[8], red_l[8];
    const int t = threadIdx.x;
    *(float4*)&sh[t * 4] = *(const float4*)&g_concat_in[(size_t)b * 2 * H_ + t * 4];
    __syncthreads();

    const int warp = t >> 5, lane = t & 31;
    float4 hn[8];
#pragma unroll
    for (int i = 0; i < 8; i++) hn[i] = *(const float4*)&sh[i * 128 + lane * 4];

    float m = -INFINITY, l = 0.f;
    float4 cv[8];
#pragma unroll
    for (int i = 0; i < 8; i++) cv[i] = make_float4(0.f, 0.f, 0.f, 0.f);

    const int sbase = chunk * 128 + warp * 16;
    for (int si = 0; si < 16; si++) {
        const int s = sbase + si;
        const float4* ep = (const float4*)(enc + ((size_t)s * B_ + b) * H_);
        float4 ev[8];
        float d = 0.f;
#pragma unroll
        for (int i = 0; i < 8; i++) {
            ev[i] = ep[i * 32 + lane];
            d = fmaf(ev[i].x, hn[i].x, d);
            d = fmaf(ev[i].y, hn[i].y, d);
            d = fmaf(ev[i].z, hn[i].z, d);
            d = fmaf(ev[i].w, hn[i].w, d);
        }
#pragma unroll
        for (int off = 16; off; off >>= 1)
            d += __shfl_xor_sync(0xffffffffu, d, off);

        if (lane == 0) g_energies[(size_t)b * S_ + s] = d;

        if (d <= m) {
            const float p = expf(d - m);
            l += p;
#pragma unroll
            for (int i = 0; i < 8; i++) {
                cv[i].x = fmaf(p, ev[i].x, cv[i].x);
                cv[i].y = fmaf(p, ev[i].y, cv[i].y);
                cv[i].z = fmaf(p, ev[i].z, cv[i].z);
                cv[i].w = fmaf(p, ev[i].w, cv[i].w);
            }
        } else {
            const float sc = expf(m - d);
            l = fmaf(l, sc, 1.f);
#pragma unroll
            for (int i = 0; i < 8; i++) {
                cv[i].x = fmaf(cv[i].x, sc, ev[i].x);
                cv[i].y = fmaf(cv[i].y, sc, ev[i].y);
                cv[i].z = fmaf(cv[i].z, sc, ev[i].z);
                cv[i].w = fmaf(cv[i].w, sc, ev[i].w);
            }
            m = d;
        }
    }

    if (lane == 0) { red_m[warp] = m; red_l[warp] = l; }
    __syncthreads();
    float M = red_m[0];
#pragma unroll
    for (int i = 1; i < 8; i++) M = fmaxf(M, red_m[i]);
    float L = 0.f;
#pragma unroll
    for (int i = 0; i < 8; i++) L += red_l[i] * expf(red_m[i] - M);

    const float wsc = expf(m - M);
#pragma unroll
    for (int i = 0; i < 8; i++) {
        float4 v = cv[i];
        v.x *= wsc; v.y *= wsc; v.z *= wsc; v.w *= wsc;
        *(float4*)&stage[warp][i * 128 + lane * 4] = v;
    }
    __syncthreads();

    float4 acc = make_float4(0.f, 0.f, 0.f, 0.f);
#pragma unroll
    for (int w = 0; w < 8; w++) {
        const float4 v = *(const float4*)&stage[w][t * 4];
        acc.x += v.x; acc.y += v.y; acc.z += v.z; acc.w += v.w;
    }
    if (t == 0) g_ml[b * 16 + chunk] = make_float2(M, L);
    ((float4*)(g_ctxp + (size_t)(b * 16 + chunk) * H_))[t] = acc;
}

// ---------------------------------------------------------------------------
// Combine the 16 per-CTA softmax partials AND emit attention weights.
// v2: 256 threads/CTA; the 16 partials are split over 4 thread-groups
// (serial load chain 16 -> 4) and reduced through smem. 4x resident warps
// vs the 12 us latency-bound 64-thread version.
// ---------------------------------------------------------------------------
__global__ __launch_bounds__(256) void attn_combine(float* __restrict__ out_attn)
{
    const int b = blockIdx.y, q = blockIdx.x, t = threadIdx.x;  // t < 256
    const int hl = t & 63, pg = t >> 6;                          // 64 h x 4 groups
    __shared__ float sm[16], sl[16];
    __shared__ float4 sred[4][64];

    if (t < 16) { float2 ml = g_ml[b * 16 + t]; sm[t] = ml.x; sl[t] = ml.y; }
    __syncthreads();

    float M = sm[0];
#pragma unroll
    for (int i = 1; i < 16; i++) M = fmaxf(M, sm[i]);
    float L = 0.f;
#pragma unroll
    for (int i = 0; i < 16; i++) L += sl[i] * expf(sm[i] - M);
    const float inv = 1.f / L;

    // each thread-group sums 4 of the 16 partials for its h-slot
    float4 acc = make_float4(0.f, 0.f, 0.f, 0.f);
    const float4* base = (const float4*)(g_ctxp + (size_t)b * 16 * H_) + q * 64 + hl;
#pragma unroll
    for (int pp = 0; pp < 4; pp++) {
        const int p = pg * 4 + pp;
        const float f = expf(sm[p] - M);
        const float4 v = base[(size_t)p * (H_ / 4)];
        acc.x = fmaf(f, v.x, acc.x);
        acc.y = fmaf(f, v.y, acc.y);
        acc.z = fmaf(f, v.z, acc.z);
        acc.w = fmaf(f, v.w, acc.w);
    }
    sred[pg][hl] = acc;
    __syncthreads();

    if (pg == 0) {
        float4 a0 = sred[0][hl], a1 = sred[1][hl], a2 = sred[2][hl], a3 = sred[3][hl];
        float4 r;
        r.x = ((a0.x + a1.x) + (a2.x + a3.x)) * inv;
        r.y = ((a0.y + a1.y) + (a2.y + a3.y)) * inv;
        r.z = ((a0.z + a1.z) + (a2.z + a3.z)) * inv;
        r.w = ((a0.w + a1.w) + (a2.w + a3.w)) * inv;
        *(float4*)&g_concat_in[(size_t)b * 2 * H_ + H_ + (q * 64 + hl) * 4] = r;
    }

    // attention-weights slice: 512 s-values per CTA over 256 threads
#pragma unroll
    for (int k = 0; k < 2; k++) {
        const int s = q * 512 + k * 256 + t;
        out_attn[(size_t)b * S_ + s] = expf(g_energies[(size_t)b * S_ + s] - M) * inv;
    }
}

// Sum concat-GEMM K-split partials (16), add bias, tanh, pre-round to tf32.
__global__ void cat_finalize(const float* __restrict__ b_concat)
{
    const int idx = blockIdx.x * blockDim.x + threadIdx.x;   // < B*H
    float v = b_concat[idx & (H_ - 1)];
#pragma unroll
    for (int p = 0; p < 16; p++) v += g_cat_part[(size_t)p * (B_ * H_) + idx];
    g_concat_out[idx] = __uint_as_float(f2tf(tanhf(v)));
}

// ---------------------------------------------------------------------------
extern "C" void kernel_launch(void* const* d_in, const int* in_sizes, int n_in,
                              void* d_out, int out_size)
{
    (void)in_sizes; (void)n_in; (void)out_size;
    const float* x    = (const float*)d_in[0];
    const float* h0   = (const float*)d_in[1];
    const float* enc  = (const float*)d_in[2];
    const float* w_ih = (const float*)d_in[3];
    const float* w_hh = (const float*)d_in[4];
    const float* b_ih = (const float*)d_in[5];
    const float* b_hh = (const float*)d_in[6];
    const float* Wc   = (const float*)d_in[7];
    const float* bc   = (const float*)d_in[8];
    const float* Wo   = (const float*)d_in[9];
    const float* bo   = (const float*)d_in[10];

    float* out        = (float*)d_out;
    float* out_output = out;                              // [B,V]
    float* out_hidden = out + (size_t)B_ * V_;            // [1,B,H]
    float* out_attn   = out_hidden + (size_t)B_ * H_;     // [B,1,S]

    void *p_cat, *p_cin, *p_cout;
    cudaGetSymbolAddress(&p_cat, g_cat_part);
    cudaGetSymbolAddress(&p_cin, g_concat_in);
    cudaGetSymbolAddress(&p_cout, g_concat_out);

    cudaFuncSetAttribute(out_gemm_v4,
                         cudaFuncAttributeMaxDynamicSharedMemorySize, OG_SMEM);

    // merged GRU GEMMs (768 CTAs, k-split x8 each)
    gemm_gru<<<dim3(48, 8, 2), 256>>>(x, h0, w_ih, w_hh);
    gru_gates<<<(B_ * H_) / 256, 256>>>(b_ih, b_hh, h0, out_hidden);

    // one-pass attention + fused combine/attn-weights
    flash_attn<<<dim3(16, B_), 256>>>(enc);
    attn_combine<<<dim3(4, B_), 256>>>(out_attn);

    // concat projection (k-split x16 -> 256 CTAs) + finalize (tf32 pre-round)
    gemm64<<<dim3(16, 16), 256>>>((const float*)p_cin, Wc, (float*)p_cat,
                                  H_, 2 * H_, 128, nullptr, 0);
    cat_finalize<<<(B_ * H_) / 256, 256>>>(bc);

    // Output GEMM: 64 x 50257 x 1024 (+bias), tf32 v4b (stride 40), 786 CTAs
    out_gemm_v4<<<(V_ + 63) / 64, 128, OG_SMEM>>>((const float*)p_cout, Wo,
                                                  bo, out_output);
}